// round 7
// baseline (speedup 1.0000x reference)
#include <cuda_runtime.h>
#include <cstdint>

// ---------------------------------------------------------------------------
// N=100000, 512 -> 16 -> 40, E=3.2M int32 edges.
// out = log_softmax( segsum(relu(segsum((xW1)[src])+b1)[src]) @ W2 + b2 )
// (W2 hoisted past the scatter by linearity of segment_sum.)
//
// ROOT CAUSE OF R2-R6: __device__ globals were passed as kernel args from
// host code; on GB300 (ATS) the host shadow address is GPU-dereferenceable,
// so scatters silently read/wrote HOST memory. Fix: kernels reference the
// globals directly in device code. Never pass them as arguments.
// ---------------------------------------------------------------------------

#define NNODES 100000
#define HID 16
#define NEDGES 3200000

__device__ __align__(16) float g_h1  [NNODES * HID];
__device__ __align__(16) float g_agg1[NNODES * HID];
__device__ __align__(16) float g_agg2[NNODES * HID];
__device__ int g_is64;

__device__ __forceinline__ void red_add_v4(float* p, float4 v) {
    asm volatile("red.global.add.v4.f32 [%0], {%1, %2, %3, %4};"
                 :: "l"(p), "f"(v.x), "f"(v.y), "f"(v.z), "f"(v.w) : "memory");
}

// ---------------------------------------------------------------------------
// detect: int64-stored indices (<2^31) have all odd 32-bit words == 0
// ---------------------------------------------------------------------------
__global__ void detect_kernel(const int* __restrict__ ei) {
    __shared__ int any_nonzero;
    if (threadIdx.x == 0) any_nonzero = 0;
    __syncthreads();
    int bad = 0;
    for (int w = 1 + 2 * threadIdx.x; w < 2048; w += 2 * blockDim.x)
        if (ei[w] != 0) bad = 1;
    if (bad) atomicOr(&any_nonzero, 1);
    __syncthreads();
    if (threadIdx.x == 0) g_is64 = (any_nonzero == 0) ? 1 : 0;
}

// ---------------------------------------------------------------------------
// 0) zero accumulators (direct global references)
// ---------------------------------------------------------------------------
__global__ void zero_kernel(int n_float4) {
    int i = blockIdx.x * blockDim.x + threadIdx.x;
    float4 z = make_float4(0.f, 0.f, 0.f, 0.f);
    if (i < n_float4) {
        reinterpret_cast<float4*>(g_agg1)[i] = z;
        reinterpret_cast<float4*>(g_agg2)[i] = z;
    }
}

// ---------------------------------------------------------------------------
// 1) h1 = x @ W1   (N x 512) @ (512 x 16)
//    One thread per row; W1 via warp-uniform __ldg (L1 broadcast).
// ---------------------------------------------------------------------------
__global__ void gemm1_kernel(const float* __restrict__ x,
                             const float* __restrict__ W1,
                             int N) {
    int row = blockIdx.x * blockDim.x + threadIdx.x;
    if (row >= N) return;

    float4 acc0 = make_float4(0.f, 0.f, 0.f, 0.f);
    float4 acc1 = acc0, acc2 = acc0, acc3 = acc0;

    const float4* xr = reinterpret_cast<const float4*>(x + (size_t)row * 512);
    const float4* Wv = reinterpret_cast<const float4*>(W1);

    for (int kk = 0; kk < 128; kk++) {
        float4 xv = __ldg(xr + kk);
        float xs[4] = {xv.x, xv.y, xv.z, xv.w};
#pragma unroll
        for (int d = 0; d < 4; d++) {
            int k = kk * 4 + d;
            float a = xs[d];
            float4 w0 = __ldg(Wv + k * 4 + 0);
            float4 w1 = __ldg(Wv + k * 4 + 1);
            float4 w2 = __ldg(Wv + k * 4 + 2);
            float4 w3 = __ldg(Wv + k * 4 + 3);
            acc0.x = fmaf(a, w0.x, acc0.x); acc0.y = fmaf(a, w0.y, acc0.y);
            acc0.z = fmaf(a, w0.z, acc0.z); acc0.w = fmaf(a, w0.w, acc0.w);
            acc1.x = fmaf(a, w1.x, acc1.x); acc1.y = fmaf(a, w1.y, acc1.y);
            acc1.z = fmaf(a, w1.z, acc1.z); acc1.w = fmaf(a, w1.w, acc1.w);
            acc2.x = fmaf(a, w2.x, acc2.x); acc2.y = fmaf(a, w2.y, acc2.y);
            acc2.z = fmaf(a, w2.z, acc2.z); acc2.w = fmaf(a, w2.w, acc2.w);
            acc3.x = fmaf(a, w3.x, acc3.x); acc3.y = fmaf(a, w3.y, acc3.y);
            acc3.z = fmaf(a, w3.z, acc3.z); acc3.w = fmaf(a, w3.w, acc3.w);
        }
    }

    float4* o = reinterpret_cast<float4*>(g_h1 + (size_t)row * 16);
    o[0] = acc0; o[1] = acc1; o[2] = acc2; o[3] = acc3;
}

// ---------------------------------------------------------------------------
// 2) scatter1: g_agg1[dst] += g_h1[src]        (direct global references)
// ---------------------------------------------------------------------------
__global__ void scatter1_kernel(const int* __restrict__ ei, int E) {
    int e = blockIdx.x * blockDim.x + threadIdx.x;
    if (e >= E) return;
    int s, d;
    if (g_is64) {
        const long long* ll = reinterpret_cast<const long long*>(ei);
        s = (int)__ldg(ll + e);
        d = (int)__ldg(ll + E + e);
    } else {
        s = __ldg(ei + e);
        d = __ldg(ei + E + e);
    }

    const float4* f = reinterpret_cast<const float4*>(g_h1 + (size_t)s * 16);
    float* o = g_agg1 + (size_t)d * 16;
    red_add_v4(o + 0,  f[0]);
    red_add_v4(o + 4,  f[1]);
    red_add_v4(o + 8,  f[2]);
    red_add_v4(o + 12, f[3]);
}

// ---------------------------------------------------------------------------
// 3) scatter2: g_agg2[dst] += relu(g_agg1[src] + b1)
// ---------------------------------------------------------------------------
__global__ void scatter2_kernel(const int* __restrict__ ei, int E,
                                const float* __restrict__ b1) {
    int e = blockIdx.x * blockDim.x + threadIdx.x;
    if (e >= E) return;
    int s, d;
    if (g_is64) {
        const long long* ll = reinterpret_cast<const long long*>(ei);
        s = (int)__ldg(ll + e);
        d = (int)__ldg(ll + E + e);
    } else {
        s = __ldg(ei + e);
        d = __ldg(ei + E + e);
    }

    const float4* f = reinterpret_cast<const float4*>(g_agg1 + (size_t)s * 16);
    const float4* bb = reinterpret_cast<const float4*>(b1);
    float* o = g_agg2 + (size_t)d * 16;
#pragma unroll
    for (int t = 0; t < 4; t++) {
        float4 v = f[t];
        float4 b = __ldg(bb + t);
        v.x = fmaxf(v.x + b.x, 0.f);
        v.y = fmaxf(v.y + b.y, 0.f);
        v.z = fmaxf(v.z + b.z, 0.f);
        v.w = fmaxf(v.w + b.w, 0.f);
        red_add_v4(o + t * 4, v);
    }
}

// ---------------------------------------------------------------------------
// 4) out = log_softmax(g_agg2 @ W2 + b2), one thread per node
// ---------------------------------------------------------------------------
__global__ void final_kernel(const float* __restrict__ W2,
                             const float* __restrict__ b2,
                             float* __restrict__ out,
                             int N) {
    int i = blockIdx.x * blockDim.x + threadIdx.x;
    if (i >= N) return;

    float a[16];
    const float4* ap = reinterpret_cast<const float4*>(g_agg2 + (size_t)i * 16);
#pragma unroll
    for (int t = 0; t < 4; t++) {
        float4 v = ap[t];
        a[t * 4 + 0] = v.x; a[t * 4 + 1] = v.y;
        a[t * 4 + 2] = v.z; a[t * 4 + 3] = v.w;
    }

    float v[40];
#pragma unroll
    for (int j = 0; j < 40; j++) v[j] = __ldg(b2 + j);
#pragma unroll
    for (int k = 0; k < 16; k++) {
        float ak = a[k];
#pragma unroll
        for (int j = 0; j < 40; j++)
            v[j] = fmaf(ak, __ldg(W2 + k * 40 + j), v[j]);   // warp-uniform
    }

    float m = v[0];
#pragma unroll
    for (int j = 1; j < 40; j++) m = fmaxf(m, v[j]);
    float ssum = 0.f;
#pragma unroll
    for (int j = 0; j < 40; j++) ssum += expf(v[j] - m);
    float lse = m + logf(ssum);

    float4* op = reinterpret_cast<float4*>(out + (size_t)i * 40);
#pragma unroll
    for (int t = 0; t < 10; t++)
        op[t] = make_float4(v[t*4+0] - lse, v[t*4+1] - lse,
                            v[t*4+2] - lse, v[t*4+3] - lse);
}

// ---------------------------------------------------------------------------
extern "C" void kernel_launch(void* const* d_in, const int* in_sizes, int n_in,
                              void* d_out, int out_size) {
    const float* x  = nullptr;
    const int*   ei = nullptr;
    const float* W1 = nullptr;
    const float* b1 = nullptr;
    const float* W2 = nullptr;
    const float* b2 = nullptr;

    for (int i = 0; i < n_in; i++) {
        int sz = in_sizes[i];
        if      (sz == 51200000)                   x  = (const float*)d_in[i];
        else if (sz == 6400000 || sz == 12800000)  ei = (const int*)d_in[i];
        else if (sz == 8192)                       W1 = (const float*)d_in[i];
        else if (sz == 16)                         b1 = (const float*)d_in[i];
        else if (sz == 640)                        W2 = (const float*)d_in[i];
        else if (sz == 40)                         b2 = (const float*)d_in[i];
    }

    const int N = NNODES;
    const int E = NEDGES;
    float* out = (float*)d_out;

    detect_kernel<<<1, 256>>>(ei);

    int nf4 = (N * HID) / 4;
    zero_kernel<<<(nf4 + 255) / 256, 256>>>(nf4);

    gemm1_kernel<<<(N + 255) / 256, 256>>>(x, W1, N);

    scatter1_kernel<<<(E + 255) / 256, 256>>>(ei, E);
    scatter2_kernel<<<(E + 255) / 256, 256>>>(ei, E, b1);

    final_kernel<<<(N + 127) / 128, 128>>>(W2, b2, out, N);
}

// round 8
// speedup vs baseline: 1.0714x; 1.0714x over previous
#include <cuda_runtime.h>
#include <cstdint>

// ---------------------------------------------------------------------------
// N=100000, 512 -> 16 -> 40, E=3.2M int32 edges.
// out = log_softmax( segsum(relu(segsum((xW1)[src])+b1)[src]) @ W2 + b2 )
// (W2 hoisted past the scatter by linearity of segment_sum.)
//
// R8: CSR counting-sort built on device each call; both aggregations are
// atomic-free warp-per-node gathers. gemm1 = smem + fma.rn.f32x2.
// RULE (R2-R6 lesson): __device__ globals are ONLY referenced inside device
// code, never passed as kernel arguments from host.
// ---------------------------------------------------------------------------

#define NNODES 100000
#define HID 16
#define NEDGES 3200000
#define NB_SCAN 391         // ceil(NNODES/256)

__device__ __align__(16) float g_h1  [NNODES * HID];
__device__ __align__(16) float g_agg1[NNODES * HID];
__device__ __align__(16) float g_agg2[NNODES * HID];
__device__ int g_cnt   [NNODES];
__device__ int g_rowptr[NNODES + 1];
__device__ int g_cursor[NNODES];
__device__ int g_esrc  [NEDGES];
__device__ int g_blksum[512];
__device__ int g_is64;

// packed f32x2 ops (PTX-only)
#define FMA_F32X2(d, a, b, c) \
    asm("fma.rn.f32x2 %0, %1, %2, %3;" : "=l"(d) : "l"(a), "l"(b), "l"(c))
#define ADD_F32X2(d, a, b) \
    asm("add.rn.f32x2 %0, %1, %2;" : "=l"(d) : "l"(a), "l"(b))

// ---------------------------------------------------------------------------
// edge index fetch (handles int32 or int64 storage, detected at runtime)
// ---------------------------------------------------------------------------
__device__ __forceinline__ int edge_at(const int* ei, int idx, int E, int half) {
    if (g_is64) {
        const long long* ll = reinterpret_cast<const long long*>(ei);
        return (int)__ldg(ll + (size_t)half * E + idx);
    }
    return __ldg(ei + (size_t)half * E + idx);
}

__global__ void detect_kernel(const int* __restrict__ ei) {
    __shared__ int any_nonzero;
    if (threadIdx.x == 0) any_nonzero = 0;
    __syncthreads();
    int bad = 0;
    for (int w = 1 + 2 * threadIdx.x; w < 2048; w += 2 * blockDim.x)
        if (ei[w] != 0) bad = 1;
    if (bad) atomicOr(&any_nonzero, 1);
    __syncthreads();
    if (threadIdx.x == 0) g_is64 = (any_nonzero == 0) ? 1 : 0;
}

// ---------------------------------------------------------------------------
// CSR build: zero counts -> histogram -> 3-kernel scan -> fill
// ---------------------------------------------------------------------------
__global__ void zero_cnt_kernel() {
    int i = blockIdx.x * blockDim.x + threadIdx.x;
    if (i < NNODES) g_cnt[i] = 0;
}

__global__ void hist_kernel(const int* __restrict__ ei, int E) {
    int e = blockIdx.x * blockDim.x + threadIdx.x;
    if (e >= E) return;
    int d = edge_at(ei, e, E, 1);
    atomicAdd(&g_cnt[d], 1);
}

__global__ void scan1_kernel() {
    __shared__ int buf[2][256];
    int t = threadIdx.x, b = blockIdx.x;
    int i = b * 256 + t;
    int v = (i < NNODES) ? g_cnt[i] : 0;
    int cur = 0;
    buf[0][t] = v;
    __syncthreads();
#pragma unroll
    for (int off = 1; off < 256; off <<= 1) {
        int x = buf[cur][t];
        if (t >= off) x += buf[cur][t - off];
        buf[cur ^ 1][t] = x;
        cur ^= 1;
        __syncthreads();
    }
    int incl = buf[cur][t];
    if (i < NNODES) g_rowptr[i] = incl - v;       // block-local exclusive
    if (t == 255) g_blksum[b] = incl;
}

__global__ void scan2_kernel() {
    __shared__ int buf[2][512];
    int t = threadIdx.x;
    int v = (t < NB_SCAN) ? g_blksum[t] : 0;
    int cur = 0;
    buf[0][t] = v;
    __syncthreads();
#pragma unroll
    for (int off = 1; off < 512; off <<= 1) {
        int x = buf[cur][t];
        if (t >= off) x += buf[cur][t - off];
        buf[cur ^ 1][t] = x;
        cur ^= 1;
        __syncthreads();
    }
    if (t < NB_SCAN) g_blksum[t] = buf[cur][t] - v;  // exclusive block offsets
}

__global__ void scan3_kernel() {
    int i = blockIdx.x * blockDim.x + threadIdx.x;
    if (i < NNODES) {
        int r = g_rowptr[i] + g_blksum[i >> 8];
        g_rowptr[i] = r;
        g_cursor[i] = r;
    }
    if (i == 0) g_rowptr[NNODES] = NEDGES;
}

__global__ void fill_kernel(const int* __restrict__ ei, int E) {
    int e = blockIdx.x * blockDim.x + threadIdx.x;
    if (e >= E) return;
    int s = edge_at(ei, e, E, 0);
    int d = edge_at(ei, e, E, 1);
    int pos = atomicAdd(&g_cursor[d], 1);
    g_esrc[pos] = s;
}

// ---------------------------------------------------------------------------
// 1) h1 = x @ W1   (N x 512)@(512 x 16); 8 lanes/row, f32x2 FMA, smem W^T
// ---------------------------------------------------------------------------
__global__ void gemm1_kernel(const float* __restrict__ x,
                             const float* __restrict__ W1) {
    __shared__ __align__(16) float Wt[16 * 512];   // Wt[j*512 + k]
    int tid = threadIdx.x;
    for (int i = tid; i < 512 * 16; i += blockDim.x) {
        int k = i >> 4, j = i & 15;
        Wt[j * 512 + k] = W1[i];
    }
    __syncthreads();

    int lane = tid & 31;
    int warp = tid >> 5;
    int gl   = lane & 7;                        // lane within 8-lane row group
    int row  = blockIdx.x * 32 + warp * 4 + (lane >> 3);

    unsigned long long acc[16];
#pragma unroll
    for (int j = 0; j < 16; j++) acc[j] = 0ull;

    if (row < NNODES) {
        const ulonglong2* xr =
            reinterpret_cast<const ulonglong2*>(x + (size_t)row * 512);
#pragma unroll 2
        for (int it = 0; it < 16; it++) {
            int kk = gl + it * 8;               // 16B chunk index
            ulonglong2 xv = __ldg(xr + kk);
            int k = kk * 4;
#pragma unroll
            for (int j = 0; j < 16; j++) {
                ulonglong2 w = *reinterpret_cast<const ulonglong2*>(&Wt[j * 512 + k]);
                FMA_F32X2(acc[j], xv.x, w.x, acc[j]);
                FMA_F32X2(acc[j], xv.y, w.y, acc[j]);
            }
        }
    }

#pragma unroll
    for (int off = 4; off >= 1; off >>= 1) {
#pragma unroll
        for (int j = 0; j < 16; j++) {
            unsigned long long o = __shfl_xor_sync(0xffffffffu, acc[j], off);
            ADD_F32X2(acc[j], acc[j], o);
        }
    }

    if (row < NNODES && gl < 4) {
        float r[4];
#pragma unroll
        for (int t = 0; t < 4; t++) {
            float2 f = *reinterpret_cast<float2*>(&acc[gl * 4 + t]);
            r[t] = f.x + f.y;
        }
        reinterpret_cast<float4*>(g_h1 + (size_t)row * 16)[gl] =
            make_float4(r[0], r[1], r[2], r[3]);
    }
}

// ---------------------------------------------------------------------------
// 2/3) CSR aggregation, warp per node: lane (q,j) q=lane>>3 handles float4
//      quarter q of edges j, j+8, ... LAYER=1: agg1 += h1[src];
//      LAYER=2: agg2 += relu(agg1[src] + b1). No atomics.
// ---------------------------------------------------------------------------
template <int LAYER>
__global__ void agg_kernel(const float* __restrict__ b1) {
    int warp = (blockIdx.x * blockDim.x + threadIdx.x) >> 5;
    if (warp >= NNODES) return;
    int lane = threadIdx.x & 31;
    int q = lane >> 3;          // which float4 of the 16 features
    int j = lane & 7;           // edge slot within warp

    int start = __ldg(&g_rowptr[warp]);
    int end   = __ldg(&g_rowptr[warp + 1]);

    float4 bq;
    if (LAYER == 2) bq = __ldg(reinterpret_cast<const float4*>(b1) + q);

    float4 acc = make_float4(0.f, 0.f, 0.f, 0.f);
    const float4* feat = reinterpret_cast<const float4*>(
        (LAYER == 1) ? g_h1 : g_agg1);

    for (int e = start + j; e < end; e += 8) {
        int s = __ldg(&g_esrc[e]);
        float4 v = __ldg(feat + (size_t)s * 4 + q);
        if (LAYER == 2) {
            v.x = fmaxf(v.x + bq.x, 0.f);
            v.y = fmaxf(v.y + bq.y, 0.f);
            v.z = fmaxf(v.z + bq.z, 0.f);
            v.w = fmaxf(v.w + bq.w, 0.f);
        }
        acc.x += v.x; acc.y += v.y; acc.z += v.z; acc.w += v.w;
    }

    // reduce over the 8 edge slots (stays within the 8-lane group)
#pragma unroll
    for (int off = 4; off >= 1; off >>= 1) {
        acc.x += __shfl_xor_sync(0xffffffffu, acc.x, off);
        acc.y += __shfl_xor_sync(0xffffffffu, acc.y, off);
        acc.z += __shfl_xor_sync(0xffffffffu, acc.z, off);
        acc.w += __shfl_xor_sync(0xffffffffu, acc.w, off);
    }

    if (j == 0) {
        float* dst = (LAYER == 1) ? g_agg1 : g_agg2;
        reinterpret_cast<float4*>(dst + (size_t)warp * 16)[q] = acc;
    }
}

// ---------------------------------------------------------------------------
// 4) out = log_softmax(g_agg2 @ W2 + b2), one thread per node
// ---------------------------------------------------------------------------
__global__ void final_kernel(const float* __restrict__ W2,
                             const float* __restrict__ b2,
                             float* __restrict__ out) {
    int i = blockIdx.x * blockDim.x + threadIdx.x;
    if (i >= NNODES) return;

    float a[16];
    const float4* ap = reinterpret_cast<const float4*>(g_agg2 + (size_t)i * 16);
#pragma unroll
    for (int t = 0; t < 4; t++) {
        float4 v = ap[t];
        a[t * 4 + 0] = v.x; a[t * 4 + 1] = v.y;
        a[t * 4 + 2] = v.z; a[t * 4 + 3] = v.w;
    }

    float v[40];
#pragma unroll
    for (int j = 0; j < 40; j++) v[j] = __ldg(b2 + j);
#pragma unroll
    for (int k = 0; k < 16; k++) {
        float ak = a[k];
#pragma unroll
        for (int j = 0; j < 40; j++)
            v[j] = fmaf(ak, __ldg(W2 + k * 40 + j), v[j]);   // warp-uniform
    }

    float m = v[0];
#pragma unroll
    for (int j = 1; j < 40; j++) m = fmaxf(m, v[j]);
    float ssum = 0.f;
#pragma unroll
    for (int j = 0; j < 40; j++) ssum += expf(v[j] - m);
    float lse = m + logf(ssum);

    float4* op = reinterpret_cast<float4*>(out + (size_t)i * 40);
#pragma unroll
    for (int t = 0; t < 10; t++)
        op[t] = make_float4(v[t*4+0] - lse, v[t*4+1] - lse,
                            v[t*4+2] - lse, v[t*4+3] - lse);
}

// ---------------------------------------------------------------------------
extern "C" void kernel_launch(void* const* d_in, const int* in_sizes, int n_in,
                              void* d_out, int out_size) {
    const float* x  = nullptr;
    const int*   ei = nullptr;
    const float* W1 = nullptr;
    const float* b1 = nullptr;
    const float* W2 = nullptr;
    const float* b2 = nullptr;

    for (int i = 0; i < n_in; i++) {
        int sz = in_sizes[i];
        if      (sz == 51200000)                   x  = (const float*)d_in[i];
        else if (sz == 6400000 || sz == 12800000)  ei = (const int*)d_in[i];
        else if (sz == 8192)                       W1 = (const float*)d_in[i];
        else if (sz == 16)                         b1 = (const float*)d_in[i];
        else if (sz == 640)                        W2 = (const float*)d_in[i];
        else if (sz == 40)                         b2 = (const float*)d_in[i];
    }

    const int E = NEDGES;
    float* out = (float*)d_out;

    detect_kernel<<<1, 256>>>(ei);

    // CSR build
    zero_cnt_kernel<<<(NNODES + 255) / 256, 256>>>();
    hist_kernel<<<(E + 255) / 256, 256>>>(ei, E);
    scan1_kernel<<<NB_SCAN, 256>>>();
    scan2_kernel<<<1, 512>>>();
    scan3_kernel<<<(NNODES + 255) / 256, 256>>>();
    fill_kernel<<<(E + 255) / 256, 256>>>(ei, E);

    // compute
    gemm1_kernel<<<(NNODES + 31) / 32, 256>>>(x, W1);
    agg_kernel<1><<<(NNODES * 32 + 255) / 256, 256>>>(nullptr);
    agg_kernel<2><<<(NNODES * 32 + 255) / 256, 256>>>(b1);
    final_kernel<<<(NNODES + 127) / 128, 128>>>(W2, b2, out);
}

// round 9
// speedup vs baseline: 1.1435x; 1.0673x over previous
#include <cuda_runtime.h>
#include <cstdint>

// ---------------------------------------------------------------------------
// N=100000, 512 -> 16 -> 40, E=3.2M int32 edges.
// out = log_softmax( segsum(relu(segsum((xW1)[src])+b1)[src]) @ W2 + b2 )
// (W2 hoisted past the scatter by linearity of segment_sum.)
//
// R9: gemm1 fully unrolled with front-batched LDGs (MLP 2 -> 16; suspected
// DRAM-latency bound). zero_kernel removed (agg writes every node).
// Launch order puts gemm1 4th: the harness profiles the 4th launch.
// RULE (R2-R6 lesson): __device__ globals are ONLY referenced inside device
// code, never passed as kernel arguments from host.
// ---------------------------------------------------------------------------

#define NNODES 100000
#define HID 16
#define NEDGES 3200000
#define NB_SCAN 391         // ceil(NNODES/256)

__device__ __align__(16) float g_h1  [NNODES * HID];
__device__ __align__(16) float g_agg1[NNODES * HID];
__device__ __align__(16) float g_agg2[NNODES * HID];
__device__ int g_cnt   [NNODES];
__device__ int g_rowptr[NNODES + 1];
__device__ int g_cursor[NNODES];
__device__ int g_esrc  [NEDGES];
__device__ int g_blksum[512];
__device__ int g_is64;

// packed f32x2 ops (PTX-only)
#define FMA_F32X2(d, a, b, c) \
    asm("fma.rn.f32x2 %0, %1, %2, %3;" : "=l"(d) : "l"(a), "l"(b), "l"(c))
#define ADD_F32X2(d, a, b) \
    asm("add.rn.f32x2 %0, %1, %2;" : "=l"(d) : "l"(a), "l"(b))

// ---------------------------------------------------------------------------
__device__ __forceinline__ int edge_at(const int* ei, int idx, int E, int half) {
    if (g_is64) {
        const long long* ll = reinterpret_cast<const long long*>(ei);
        return (int)__ldg(ll + (size_t)half * E + idx);
    }
    return __ldg(ei + (size_t)half * E + idx);
}

__global__ void detect_kernel(const int* __restrict__ ei) {
    __shared__ int any_nonzero;
    if (threadIdx.x == 0) any_nonzero = 0;
    __syncthreads();
    int bad = 0;
    for (int w = 1 + 2 * threadIdx.x; w < 2048; w += 2 * blockDim.x)
        if (ei[w] != 0) bad = 1;
    if (bad) atomicOr(&any_nonzero, 1);
    __syncthreads();
    if (threadIdx.x == 0) g_is64 = (any_nonzero == 0) ? 1 : 0;
}

// ---------------------------------------------------------------------------
// CSR build
// ---------------------------------------------------------------------------
__global__ void zero_cnt_kernel() {
    int i = blockIdx.x * blockDim.x + threadIdx.x;
    if (i < NNODES) g_cnt[i] = 0;
}

__global__ void hist_kernel(const int* __restrict__ ei, int E) {
    int e = blockIdx.x * blockDim.x + threadIdx.x;
    if (e >= E) return;
    int d = edge_at(ei, e, E, 1);
    atomicAdd(&g_cnt[d], 1);
}

__global__ void scan1_kernel() {
    __shared__ int buf[2][256];
    int t = threadIdx.x, b = blockIdx.x;
    int i = b * 256 + t;
    int v = (i < NNODES) ? g_cnt[i] : 0;
    int cur = 0;
    buf[0][t] = v;
    __syncthreads();
#pragma unroll
    for (int off = 1; off < 256; off <<= 1) {
        int x = buf[cur][t];
        if (t >= off) x += buf[cur][t - off];
        buf[cur ^ 1][t] = x;
        cur ^= 1;
        __syncthreads();
    }
    int incl = buf[cur][t];
    if (i < NNODES) g_rowptr[i] = incl - v;
    if (t == 255) g_blksum[b] = incl;
}

__global__ void scan2_kernel() {
    __shared__ int buf[2][512];
    int t = threadIdx.x;
    int v = (t < NB_SCAN) ? g_blksum[t] : 0;
    int cur = 0;
    buf[0][t] = v;
    __syncthreads();
#pragma unroll
    for (int off = 1; off < 512; off <<= 1) {
        int x = buf[cur][t];
        if (t >= off) x += buf[cur][t - off];
        buf[cur ^ 1][t] = x;
        cur ^= 1;
        __syncthreads();
    }
    if (t < NB_SCAN) g_blksum[t] = buf[cur][t] - v;
}

__global__ void scan3_kernel() {
    int i = blockIdx.x * blockDim.x + threadIdx.x;
    if (i < NNODES) {
        int r = g_rowptr[i] + g_blksum[i >> 8];
        g_rowptr[i] = r;
        g_cursor[i] = r;
    }
    if (i == 0) g_rowptr[NNODES] = NEDGES;
}

__global__ void fill_kernel(const int* __restrict__ ei, int E) {
    int e = blockIdx.x * blockDim.x + threadIdx.x;
    if (e >= E) return;
    int s = edge_at(ei, e, E, 0);
    int d = edge_at(ei, e, E, 1);
    int pos = atomicAdd(&g_cursor[d], 1);
    g_esrc[pos] = s;
}

// ---------------------------------------------------------------------------
// 1) h1 = x @ W1  — 8 lanes/row, FULLY UNROLLED front-batched LDGs (MLP=16),
//    f32x2 FMA against transposed W in smem.
// ---------------------------------------------------------------------------
__global__ void __launch_bounds__(256) gemm1_kernel(const float* __restrict__ x,
                                                    const float* __restrict__ W1) {
    __shared__ __align__(16) float Wt[16 * 512];   // Wt[j*512 + k]
    int tid = threadIdx.x;
    for (int i = tid; i < 512 * 16; i += blockDim.x) {
        int k = i >> 4, j = i & 15;
        Wt[j * 512 + k] = W1[i];
    }
    __syncthreads();

    int lane = tid & 31;
    int warp = tid >> 5;
    int gl   = lane & 7;                        // lane within 8-lane row group
    int row  = blockIdx.x * 32 + warp * 4 + (lane >> 3);
    bool live = (row < NNODES);
    int srow = live ? row : (NNODES - 1);       // safe row for dead lanes

    const ulonglong2* xr =
        reinterpret_cast<const ulonglong2*>(x + (size_t)srow * 512);

    // front-batch all 16 LDG.128s (256B per lane in flight)
    ulonglong2 xv[16];
#pragma unroll
    for (int it = 0; it < 16; it++)
        xv[it] = __ldg(xr + gl + it * 8);

    unsigned long long acc[16];
#pragma unroll
    for (int j = 0; j < 16; j++) acc[j] = 0ull;

#pragma unroll
    for (int it = 0; it < 16; it++) {
        int k = (gl + it * 8) * 4;
#pragma unroll
        for (int j = 0; j < 16; j++) {
            ulonglong2 w = *reinterpret_cast<const ulonglong2*>(&Wt[j * 512 + k]);
            FMA_F32X2(acc[j], xv[it].x, w.x, acc[j]);
            FMA_F32X2(acc[j], xv[it].y, w.y, acc[j]);
        }
    }

#pragma unroll
    for (int off = 4; off >= 1; off >>= 1) {
#pragma unroll
        for (int j = 0; j < 16; j++) {
            unsigned long long o = __shfl_xor_sync(0xffffffffu, acc[j], off);
            ADD_F32X2(acc[j], acc[j], o);
        }
    }

    if (live && gl < 4) {
        float r[4];
#pragma unroll
        for (int t = 0; t < 4; t++) {
            float2 f = *reinterpret_cast<float2*>(&acc[gl * 4 + t]);
            r[t] = f.x + f.y;
        }
        reinterpret_cast<float4*>(g_h1 + (size_t)row * 16)[gl] =
            make_float4(r[0], r[1], r[2], r[3]);
    }
}

// ---------------------------------------------------------------------------
// 2/3) CSR aggregation, warp per node (writes EVERY node -> no pre-zero).
// ---------------------------------------------------------------------------
template <int LAYER>
__global__ void agg_kernel(const float* __restrict__ b1) {
    int warp = (blockIdx.x * blockDim.x + threadIdx.x) >> 5;
    if (warp >= NNODES) return;
    int lane = threadIdx.x & 31;
    int q = lane >> 3;
    int j = lane & 7;

    int start = __ldg(&g_rowptr[warp]);
    int end   = __ldg(&g_rowptr[warp + 1]);

    float4 bq;
    if (LAYER == 2) bq = __ldg(reinterpret_cast<const float4*>(b1) + q);

    float4 acc = make_float4(0.f, 0.f, 0.f, 0.f);
    const float4* feat = reinterpret_cast<const float4*>(
        (LAYER == 1) ? g_h1 : g_agg1);

    for (int e = start + j; e < end; e += 8) {
        int s = __ldg(&g_esrc[e]);
        float4 v = __ldg(feat + (size_t)s * 4 + q);
        if (LAYER == 2) {
            v.x = fmaxf(v.x + bq.x, 0.f);
            v.y = fmaxf(v.y + bq.y, 0.f);
            v.z = fmaxf(v.z + bq.z, 0.f);
            v.w = fmaxf(v.w + bq.w, 0.f);
        }
        acc.x += v.x; acc.y += v.y; acc.z += v.z; acc.w += v.w;
    }

#pragma unroll
    for (int off = 4; off >= 1; off >>= 1) {
        acc.x += __shfl_xor_sync(0xffffffffu, acc.x, off);
        acc.y += __shfl_xor_sync(0xffffffffu, acc.y, off);
        acc.z += __shfl_xor_sync(0xffffffffu, acc.z, off);
        acc.w += __shfl_xor_sync(0xffffffffu, acc.w, off);
    }

    if (j == 0) {
        float* dst = (LAYER == 1) ? g_agg1 : g_agg2;
        reinterpret_cast<float4*>(dst + (size_t)warp * 16)[q] = acc;
    }
}

// ---------------------------------------------------------------------------
// 4) out = log_softmax(g_agg2 @ W2 + b2)
// ---------------------------------------------------------------------------
__global__ void final_kernel(const float* __restrict__ W2,
                             const float* __restrict__ b2,
                             float* __restrict__ out) {
    int i = blockIdx.x * blockDim.x + threadIdx.x;
    if (i >= NNODES) return;

    float a[16];
    const float4* ap = reinterpret_cast<const float4*>(g_agg2 + (size_t)i * 16);
#pragma unroll
    for (int t = 0; t < 4; t++) {
        float4 v = ap[t];
        a[t * 4 + 0] = v.x; a[t * 4 + 1] = v.y;
        a[t * 4 + 2] = v.z; a[t * 4 + 3] = v.w;
    }

    float v[40];
#pragma unroll
    for (int j = 0; j < 40; j++) v[j] = __ldg(b2 + j);
#pragma unroll
    for (int k = 0; k < 16; k++) {
        float ak = a[k];
#pragma unroll
        for (int j = 0; j < 40; j++)
            v[j] = fmaf(ak, __ldg(W2 + k * 40 + j), v[j]);
    }

    float m = v[0];
#pragma unroll
    for (int j = 1; j < 40; j++) m = fmaxf(m, v[j]);
    float ssum = 0.f;
#pragma unroll
    for (int j = 0; j < 40; j++) ssum += expf(v[j] - m);
    float lse = m + logf(ssum);

    float4* op = reinterpret_cast<float4*>(out + (size_t)i * 40);
#pragma unroll
    for (int t = 0; t < 10; t++)
        op[t] = make_float4(v[t*4+0] - lse, v[t*4+1] - lse,
                            v[t*4+2] - lse, v[t*4+3] - lse);
}

// ---------------------------------------------------------------------------
extern "C" void kernel_launch(void* const* d_in, const int* in_sizes, int n_in,
                              void* d_out, int out_size) {
    const float* x  = nullptr;
    const int*   ei = nullptr;
    const float* W1 = nullptr;
    const float* b1 = nullptr;
    const float* W2 = nullptr;
    const float* b2 = nullptr;

    for (int i = 0; i < n_in; i++) {
        int sz = in_sizes[i];
        if      (sz == 51200000)                   x  = (const float*)d_in[i];
        else if (sz == 6400000 || sz == 12800000)  ei = (const int*)d_in[i];
        else if (sz == 8192)                       W1 = (const float*)d_in[i];
        else if (sz == 16)                         b1 = (const float*)d_in[i];
        else if (sz == 640)                        W2 = (const float*)d_in[i];
        else if (sz == 40)                         b2 = (const float*)d_in[i];
    }

    const int E = NEDGES;
    float* out = (float*)d_out;

    detect_kernel<<<1, 256>>>(ei);                            // 1
    zero_cnt_kernel<<<(NNODES + 255) / 256, 256>>>();         // 2
    hist_kernel<<<(E + 255) / 256, 256>>>(ei, E);             // 3
    gemm1_kernel<<<(NNODES + 31) / 32, 256>>>(x, W1);         // 4  <- profiled
    scan1_kernel<<<NB_SCAN, 256>>>();                         // 5
    scan2_kernel<<<1, 512>>>();                               // 6
    scan3_kernel<<<(NNODES + 255) / 256, 256>>>();            // 7
    fill_kernel<<<(E + 255) / 256, 256>>>(ei, E);             // 8
    agg_kernel<1><<<(NNODES * 32 + 255) / 256, 256>>>(nullptr); // 9
    agg_kernel<2><<<(NNODES * 32 + 255) / 256, 256>>>(b1);    // 10
    final_kernel<<<(NNODES + 127) / 128, 128>>>(W2, b2, out); // 11
}

// round 10
// speedup vs baseline: 1.3331x; 1.1658x over previous
#include <cuda_runtime.h>
#include <cstdint>

// ---------------------------------------------------------------------------
// N=100000, 512 -> 16 -> 40, E=3.2M int32 edges.
// out = log_softmax( segsum(relu(segsum((xW1)[src])+b1)[src]) @ W2 + b2 )
// (W2 hoisted past the scatter by linearity of segment_sum.)
//
// R10: gemm1 register-blocked. R9 ncu: L1(LDS)=93% -> each lane re-read all
// of W (3.2GB LDS). Now: warp=16 rows, lane=(rg 0..3, kg 0..7); 4 rows/lane,
// 64 k per kg-lane; W smem padded so kg-lanes are bank-conflict-free.
// LDS traffic /4, FMA via f32x2 col-pairs. Everything else unchanged.
// RULE: __device__ globals only referenced in device code (ATS trap).
// ---------------------------------------------------------------------------

#define NNODES 100000
#define HID 16
#define NEDGES 3200000
#define NB_SCAN 391         // ceil(NNODES/256)

__device__ __align__(16) float g_h1  [NNODES * HID];
__device__ __align__(16) float g_agg1[NNODES * HID];
__device__ __align__(16) float g_agg2[NNODES * HID];
__device__ int g_cnt   [NNODES];
__device__ int g_rowptr[NNODES + 1];
__device__ int g_cursor[NNODES];
__device__ int g_esrc  [NEDGES];
__device__ int g_blksum[512];
__device__ int g_is64;

// packed f32x2 ops (PTX-only)
#define FMA_F32X2(d, a, b, c) \
    asm("fma.rn.f32x2 %0, %1, %2, %3;" : "=l"(d) : "l"(a), "l"(b), "l"(c))
#define ADD_F32X2(d, a, b) \
    asm("add.rn.f32x2 %0, %1, %2;" : "=l"(d) : "l"(a), "l"(b))
#define PACK2(d, s) \
    asm("mov.b64 %0, {%1, %1};" : "=l"(d) : "r"(__float_as_uint(s)))

// ---------------------------------------------------------------------------
__device__ __forceinline__ int edge_at(const int* ei, int idx, int E, int half) {
    if (g_is64) {
        const long long* ll = reinterpret_cast<const long long*>(ei);
        return (int)__ldg(ll + (size_t)half * E + idx);
    }
    return __ldg(ei + (size_t)half * E + idx);
}

__global__ void detect_kernel(const int* __restrict__ ei) {
    __shared__ int any_nonzero;
    if (threadIdx.x == 0) any_nonzero = 0;
    __syncthreads();
    int bad = 0;
    for (int w = 1 + 2 * threadIdx.x; w < 2048; w += 2 * blockDim.x)
        if (ei[w] != 0) bad = 1;
    if (bad) atomicOr(&any_nonzero, 1);
    __syncthreads();
    if (threadIdx.x == 0) g_is64 = (any_nonzero == 0) ? 1 : 0;
}

// ---------------------------------------------------------------------------
// CSR build
// ---------------------------------------------------------------------------
__global__ void zero_cnt_kernel() {
    int i = blockIdx.x * blockDim.x + threadIdx.x;
    if (i < NNODES) g_cnt[i] = 0;
}

__global__ void hist_kernel(const int* __restrict__ ei, int E) {
    int e = blockIdx.x * blockDim.x + threadIdx.x;
    if (e >= E) return;
    int d = edge_at(ei, e, E, 1);
    atomicAdd(&g_cnt[d], 1);
}

__global__ void scan1_kernel() {
    __shared__ int buf[2][256];
    int t = threadIdx.x, b = blockIdx.x;
    int i = b * 256 + t;
    int v = (i < NNODES) ? g_cnt[i] : 0;
    int cur = 0;
    buf[0][t] = v;
    __syncthreads();
#pragma unroll
    for (int off = 1; off < 256; off <<= 1) {
        int x = buf[cur][t];
        if (t >= off) x += buf[cur][t - off];
        buf[cur ^ 1][t] = x;
        cur ^= 1;
        __syncthreads();
    }
    int incl = buf[cur][t];
    if (i < NNODES) g_rowptr[i] = incl - v;
    if (t == 255) g_blksum[b] = incl;
}

__global__ void scan2_kernel() {
    __shared__ int buf[2][512];
    int t = threadIdx.x;
    int v = (t < NB_SCAN) ? g_blksum[t] : 0;
    int cur = 0;
    buf[0][t] = v;
    __syncthreads();
#pragma unroll
    for (int off = 1; off < 512; off <<= 1) {
        int x = buf[cur][t];
        if (t >= off) x += buf[cur][t - off];
        buf[cur ^ 1][t] = x;
        cur ^= 1;
        __syncthreads();
    }
    if (t < NB_SCAN) g_blksum[t] = buf[cur][t] - v;
}

__global__ void scan3_kernel() {
    int i = blockIdx.x * blockDim.x + threadIdx.x;
    if (i < NNODES) {
        int r = g_rowptr[i] + g_blksum[i >> 8];
        g_rowptr[i] = r;
        g_cursor[i] = r;
    }
    if (i == 0) g_rowptr[NNODES] = NEDGES;
}

__global__ void fill_kernel(const int* __restrict__ ei, int E) {
    int e = blockIdx.x * blockDim.x + threadIdx.x;
    if (e >= E) return;
    int s = edge_at(ei, e, E, 0);
    int d = edge_at(ei, e, E, 1);
    int pos = atomicAdd(&g_cursor[d], 1);
    g_esrc[pos] = s;
}

// ---------------------------------------------------------------------------
// 1) h1 = x @ W1  — register-blocked: warp = 16 rows; lane=(rg,kg):
//    4 rows, k in [kg*64,(kg+1)*64). acc[r][jp] = f32x2 over col pair.
//    W smem layout: Ws[kg*1028 + kk*16 + j]  (pad 4 -> kg lanes hit banks
//    {0,4,..,28}: warp's 8 LDS.128 addresses tile all 32 banks).
// ---------------------------------------------------------------------------
#define WS_STRIDE 1028
__global__ void __launch_bounds__(128) gemm1_kernel(const float* __restrict__ x,
                                                    const float* __restrict__ W1) {
    __shared__ __align__(16) float Ws[8 * WS_STRIDE];
    int tid = threadIdx.x;
    for (int i = tid; i < 8192; i += blockDim.x) {
        int k = i >> 4, j = i & 15;
        Ws[(k >> 6) * WS_STRIDE + (k & 63) * 16 + j] = W1[i];
    }
    __syncthreads();

    int lane = tid & 31;
    int wrp  = tid >> 5;
    int gw   = blockIdx.x * 4 + wrp;            // global warp id
    if (gw >= NNODES / 16) return;              // 6250 warps exactly
    int rg = lane >> 3;                         // row group 0..3
    int kg = lane & 7;                          // k group   0..7
    int row0 = gw * 16 + rg * 4;                // 4 rows: row0..row0+3

    const float4* xv = reinterpret_cast<const float4*>(x);
    const float4* wsv = reinterpret_cast<const float4*>(Ws + kg * WS_STRIDE);

    unsigned long long acc[32];                 // [r*8 + jp]
#pragma unroll
    for (int i = 0; i < 32; i++) acc[i] = 0ull;

#pragma unroll
    for (int c = 0; c < 8; c++) {               // 8 chunks of 8 k
        // front-batch x: 4 rows x 8 floats
        float x8[4][8];
#pragma unroll
        for (int r = 0; r < 3 + 1; r++) {
            size_t base = (size_t)(row0 + r) * 128 + kg * 16 + c * 2;
            float4 a = __ldg(xv + base);
            float4 b = __ldg(xv + base + 1);
            x8[r][0]=a.x; x8[r][1]=a.y; x8[r][2]=a.z; x8[r][3]=a.w;
            x8[r][4]=b.x; x8[r][5]=b.y; x8[r][6]=b.z; x8[r][7]=b.w;
        }
#pragma unroll
        for (int ki = 0; ki < 8; ki++) {
            int kk = c * 8 + ki;
            // W row kk: 16 cols = 4 float4 = 8 col-pairs
            float4 w0 = wsv[kk * 4 + 0];
            float4 w1 = wsv[kk * 4 + 1];
            float4 w2 = wsv[kk * 4 + 2];
            float4 w3 = wsv[kk * 4 + 3];
            unsigned long long wp[8];
            wp[0] = *reinterpret_cast<unsigned long long*>(&w0.x);
            wp[1] = *reinterpret_cast<unsigned long long*>(&w0.z);
            wp[2] = *reinterpret_cast<unsigned long long*>(&w1.x);
            wp[3] = *reinterpret_cast<unsigned long long*>(&w1.z);
            wp[4] = *reinterpret_cast<unsigned long long*>(&w2.x);
            wp[5] = *reinterpret_cast<unsigned long long*>(&w2.z);
            wp[6] = *reinterpret_cast<unsigned long long*>(&w3.x);
            wp[7] = *reinterpret_cast<unsigned long long*>(&w3.z);
#pragma unroll
            for (int r = 0; r < 4; r++) {
                unsigned long long xx;
                PACK2(xx, x8[r][ki]);
#pragma unroll
                for (int jp = 0; jp < 8; jp++)
                    FMA_F32X2(acc[r * 8 + jp], xx, wp[jp], acc[r * 8 + jp]);
            }
        }
    }

    // reduce across the 8 kg lanes (xor within 8-lane group)
#pragma unroll
    for (int off = 4; off >= 1; off >>= 1) {
#pragma unroll
        for (int i = 0; i < 32; i++) {
            unsigned long long o = __shfl_xor_sync(0xffffffffu, acc[i], off);
            ADD_F32X2(acc[i], acc[i], o);
        }
    }

    if (kg == 0) {
#pragma unroll
        for (int r = 0; r < 4; r++) {
            float4* o = reinterpret_cast<float4*>(g_h1 + (size_t)(row0 + r) * 16);
#pragma unroll
            for (int t = 0; t < 4; t++) {
                float2 lo = *reinterpret_cast<float2*>(&acc[r * 8 + t * 2]);
                float2 hi = *reinterpret_cast<float2*>(&acc[r * 8 + t * 2 + 1]);
                o[t] = make_float4(lo.x, lo.y, hi.x, hi.y);
            }
        }
    }
}

// ---------------------------------------------------------------------------
// 2/3) CSR aggregation, warp per node (writes EVERY node -> no pre-zero).
// ---------------------------------------------------------------------------
template <int LAYER>
__global__ void agg_kernel(const float* __restrict__ b1) {
    int warp = (blockIdx.x * blockDim.x + threadIdx.x) >> 5;
    if (warp >= NNODES) return;
    int lane = threadIdx.x & 31;
    int q = lane >> 3;
    int j = lane & 7;

    int start = __ldg(&g_rowptr[warp]);
    int end   = __ldg(&g_rowptr[warp + 1]);

    float4 bq;
    if (LAYER == 2) bq = __ldg(reinterpret_cast<const float4*>(b1) + q);

    float4 acc = make_float4(0.f, 0.f, 0.f, 0.f);
    const float4* feat = reinterpret_cast<const float4*>(
        (LAYER == 1) ? g_h1 : g_agg1);

    for (int e = start + j; e < end; e += 8) {
        int s = __ldg(&g_esrc[e]);
        float4 v = __ldg(feat + (size_t)s * 4 + q);
        if (LAYER == 2) {
            v.x = fmaxf(v.x + bq.x, 0.f);
            v.y = fmaxf(v.y + bq.y, 0.f);
            v.z = fmaxf(v.z + bq.z, 0.f);
            v.w = fmaxf(v.w + bq.w, 0.f);
        }
        acc.x += v.x; acc.y += v.y; acc.z += v.z; acc.w += v.w;
    }

#pragma unroll
    for (int off = 4; off >= 1; off >>= 1) {
        acc.x += __shfl_xor_sync(0xffffffffu, acc.x, off);
        acc.y += __shfl_xor_sync(0xffffffffu, acc.y, off);
        acc.z += __shfl_xor_sync(0xffffffffu, acc.z, off);
        acc.w += __shfl_xor_sync(0xffffffffu, acc.w, off);
    }

    if (j == 0) {
        float* dst = (LAYER == 1) ? g_agg1 : g_agg2;
        reinterpret_cast<float4*>(dst + (size_t)warp * 16)[q] = acc;
    }
}

// ---------------------------------------------------------------------------
// 4) out = log_softmax(g_agg2 @ W2 + b2)
// ---------------------------------------------------------------------------
__global__ void final_kernel(const float* __restrict__ W2,
                             const float* __restrict__ b2,
                             float* __restrict__ out) {
    int i = blockIdx.x * blockDim.x + threadIdx.x;
    if (i >= NNODES) return;

    float a[16];
    const float4* ap = reinterpret_cast<const float4*>(g_agg2 + (size_t)i * 16);
#pragma unroll
    for (int t = 0; t < 4; t++) {
        float4 v = ap[t];
        a[t * 4 + 0] = v.x; a[t * 4 + 1] = v.y;
        a[t * 4 + 2] = v.z; a[t * 4 + 3] = v.w;
    }

    float v[40];
#pragma unroll
    for (int j = 0; j < 40; j++) v[j] = __ldg(b2 + j);
#pragma unroll
    for (int k = 0; k < 16; k++) {
        float ak = a[k];
#pragma unroll
        for (int j = 0; j < 40; j++)
            v[j] = fmaf(ak, __ldg(W2 + k * 40 + j), v[j]);
    }

    float m = v[0];
#pragma unroll
    for (int j = 1; j < 40; j++) m = fmaxf(m, v[j]);
    float ssum = 0.f;
#pragma unroll
    for (int j = 0; j < 40; j++) ssum += expf(v[j] - m);
    float lse = m + logf(ssum);

    float4* op = reinterpret_cast<float4*>(out + (size_t)i * 40);
#pragma unroll
    for (int t = 0; t < 10; t++)
        op[t] = make_float4(v[t*4+0] - lse, v[t*4+1] - lse,
                            v[t*4+2] - lse, v[t*4+3] - lse);
}

// ---------------------------------------------------------------------------
extern "C" void kernel_launch(void* const* d_in, const int* in_sizes, int n_in,
                              void* d_out, int out_size) {
    const float* x  = nullptr;
    const int*   ei = nullptr;
    const float* W1 = nullptr;
    const float* b1 = nullptr;
    const float* W2 = nullptr;
    const float* b2 = nullptr;

    for (int i = 0; i < n_in; i++) {
        int sz = in_sizes[i];
        if      (sz == 51200000)                   x  = (const float*)d_in[i];
        else if (sz == 6400000 || sz == 12800000)  ei = (const int*)d_in[i];
        else if (sz == 8192)                       W1 = (const float*)d_in[i];
        else if (sz == 16)                         b1 = (const float*)d_in[i];
        else if (sz == 640)                        W2 = (const float*)d_in[i];
        else if (sz == 40)                         b2 = (const float*)d_in[i];
    }

    const int E = NEDGES;
    float* out = (float*)d_out;

    detect_kernel<<<1, 256>>>(ei);                            // 1
    zero_cnt_kernel<<<(NNODES + 255) / 256, 256>>>();         // 2
    hist_kernel<<<(E + 255) / 256, 256>>>(ei, E);             // 3
    gemm1_kernel<<<1563, 128>>>(x, W1);                       // 4  <- profiled
    scan1_kernel<<<NB_SCAN, 256>>>();                         // 5
    scan2_kernel<<<1, 512>>>();                               // 6
    scan3_kernel<<<(NNODES + 255) / 256, 256>>>();            // 7
    fill_kernel<<<(E + 255) / 256, 256>>>(ei, E);             // 8
    agg_kernel<1><<<(NNODES * 32 + 255) / 256, 256>>>(nullptr); // 9
    agg_kernel<2><<<(NNODES * 32 + 255) / 256, 256>>>(b1);    // 10
    final_kernel<<<(NNODES + 127) / 128, 128>>>(W2, b2, out); // 11
}